// round 6
// baseline (speedup 1.0000x reference)
#include <cuda_runtime.h>
#include <cstdint>

// Problem constants (fixed by setup_inputs)
#define B 8
#define L 2048
#define H 8
#define D 64
#define BH (B*H)

// Scratch (device globals — no allocation allowed)
__device__ float g_M[BH * L];        // sparsity measure per (b,h,q)
__device__ int   g_top[BH * 64];     // top-u query indices per (b,h)  (u <= 64)
__device__ float g_vmean[BH * D];    // mean of V over L per (b,h,d)

// ---------------------------------------------------------------------------
// Kernel A v2: M[b,h,q] = max_s(QK_s) - mean_s(QK_s), K staged through smem.
// Block = (bh, q-tile of 256). 512 threads = 16 warps, 16 queries per warp.
// K streamed in 8 chunks of 256 keys (64KB smem). Samples matched to the
// resident chunk via ballot; two samples reduced per butterfly pass.
// ---------------------------------------------------------------------------
#define CHUNK 256
#define CSHIFT 8                 // log2(CHUNK)
#define NCH (L / CHUNK)          // 8
#define QT 256                   // queries per block
#define KA_THREADS 512
#define QPW (QT / (KA_THREADS/32))   // 16 queries per warp
#define SMEM_A (CHUNK * D * 4)   // 64 KB

__global__ void __launch_bounds__(KA_THREADS) kA_mscore(
    const float* __restrict__ Q, const float* __restrict__ K,
    const int* __restrict__ idx, int SK)
{
    extern __shared__ float sK[];   // [CHUNK][D]
    const unsigned F = 0xffffffffu;
    int t = threadIdx.x, w = t >> 5, lane = t & 31;
    int bh = blockIdx.x >> 3;       // 8 q-tiles per bh
    int qt = blockIdx.x & 7;
    int b = bh >> 3, h = bh & 7;
    int qbase = qt * QT + w * QPW;

    float mx[QPW], sm[QPW];
    #pragma unroll
    for (int j = 0; j < QPW; ++j) { mx[j] = -3.402823466e38f; sm[j] = 0.f; }

    for (int c = 0; c < NCH; ++c) {
        if (c) __syncthreads();
        // cooperative load of K chunk (CHUNK rows x 16 float4)
        for (int i = t; i < CHUNK * (D/4); i += KA_THREADS) {
            int r = i >> 4, dc = i & 15;
            ((float4*)sK)[i] =
                *(const float4*)&K[((size_t)(b*L + c*CHUNK + r)*H + h)*D + dc*4];
        }
        __syncthreads();

        #pragma unroll
        for (int j = 0; j < QPW; ++j) {
            int q = qbase + j;
            float2 qv = *(const float2*)&Q[((size_t)(b*L + q)*H + h)*D + lane*2];
            const int* ip = idx + (size_t)q * SK;
            int kq0 = (lane      < SK) ? ip[lane]      : -1;
            int kq1 = (lane + 32 < SK) ? ip[lane + 32] : -1;
            unsigned m0 = __ballot_sync(F, (kq0 >> CSHIFT) == c);
            unsigned m1 = __ballot_sync(F, (kq1 >> CSHIFT) == c);
            unsigned long long mask =
                (unsigned long long)m0 | ((unsigned long long)m1 << 32);

            while (mask) {
                int s0 = __ffsll((long long)mask) - 1; mask &= mask - 1;
                int s1valid = (mask != 0ull);
                int s1 = 0;
                if (s1valid) { s1 = __ffsll((long long)mask) - 1; mask &= mask - 1; }
                int ka = __shfl_sync(F, (s0 < 32) ? kq0 : kq1, s0 & 31);
                int kb = __shfl_sync(F, (s1 < 32) ? kq0 : kq1, s1 & 31);
                float2 k0 = *(const float2*)&sK[(ka & (CHUNK-1)) * D + lane*2];
                float2 k1 = *(const float2*)&sK[(kb & (CHUNK-1)) * D + lane*2];
                float v0 = qv.x * k0.x + qv.y * k0.y;
                float v1 = qv.x * k1.x + qv.y * k1.y;
                // pair butterfly: after xor-16, lanes<16 carry A, lanes>=16 carry B
                v0 += __shfl_xor_sync(F, v0, 16);
                v1 += __shfl_xor_sync(F, v1, 16);
                float x = (lane < 16) ? v0 : v1;
                x += __shfl_xor_sync(F, x, 8);
                x += __shfl_xor_sync(F, x, 4);
                x += __shfl_xor_sync(F, x, 2);
                x += __shfl_xor_sync(F, x, 1);
                // x: lanes 0-15 = total(A) ; lanes 16-31 = total(B)
                bool use = (lane < 16) || s1valid;
                if (use) mx[j] = fmaxf(mx[j], x);
                sm[j] += use ? x : 0.f;
            }
        }
    }

    // Each sample total lives on exactly 16 lanes -> cross-lane sum / 16.
    #pragma unroll
    for (int j = 0; j < QPW; ++j) {
        float m = mx[j], s = sm[j];
        #pragma unroll
        for (int o = 16; o; o >>= 1) {
            m = fmaxf(m, __shfl_xor_sync(F, m, o));
            s += __shfl_xor_sync(F, s, o);
        }
        if (lane == 0)
            g_M[(size_t)bh * L + qbase + j] = m - (s * (1.0f/16.0f)) / (float)SK;
    }
}

// ---------------------------------------------------------------------------
// Kernel B v2: top-U per (b,h) with register-resident 64-bit sortable keys.
// key = (ordered(value) << 32) | ~index  -> max picks higher value, lower idx.
// ---------------------------------------------------------------------------
__global__ void __launch_bounds__(256) kB_topk(int U)
{
    __shared__ unsigned long long warpbest[8];
    __shared__ unsigned long long sbest;
    int bh = blockIdx.x, t = threadIdx.x, lane = t & 31, w = t >> 5;

    unsigned long long key[8];
    #pragma unroll
    for (int i = 0; i < 8; ++i) {
        int q = t + i * 256;
        unsigned u = __float_as_uint(g_M[(size_t)bh * L + q]);
        u ^= (u >> 31) ? 0xffffffffu : 0x80000000u;
        key[i] = ((unsigned long long)u << 32) | (unsigned)(~q);
    }

    for (int it = 0; it < U; ++it) {
        unsigned long long best = 0;
        #pragma unroll
        for (int i = 0; i < 8; ++i) best = (key[i] > best) ? key[i] : best;
        #pragma unroll
        for (int o = 16; o; o >>= 1) {
            unsigned long long oth = __shfl_xor_sync(0xffffffffu, best, o);
            best = (oth > best) ? oth : best;
        }
        if (lane == 0) warpbest[w] = best;
        __syncthreads();
        if (t < 32) {
            unsigned long long bb = (t < 8) ? warpbest[t] : 0ull;
            #pragma unroll
            for (int o = 4; o; o >>= 1) {
                unsigned long long oth = __shfl_xor_sync(0xffffffffu, bb, o);
                bb = (oth > bb) ? oth : bb;
            }
            if (t == 0) {
                sbest = bb;
                g_top[bh * 64 + it] = (int)(~(unsigned)(bb & 0xffffffffu));
            }
        }
        __syncthreads();
        unsigned long long win = sbest;
        #pragma unroll
        for (int i = 0; i < 8; ++i) if (key[i] == win) key[i] = 0ull;
    }
}

// ---------------------------------------------------------------------------
// Kernel C: Vmean[b,h,d] = mean over l of V[b,l,h,d]. One block per (b,h).
// ---------------------------------------------------------------------------
__global__ void __launch_bounds__(256) kC_vmean(const float* __restrict__ V)
{
    __shared__ float part[4][D];
    int bh = blockIdx.x, b = bh >> 3, h = bh & 7;
    int d = threadIdx.x & 63, g = threadIdx.x >> 6;
    float s = 0.f;
    for (int l = g; l < L; l += 4)
        s += V[((size_t)(b * L + l) * H + h) * D + d];
    part[g][d] = s;
    __syncthreads();
    if (threadIdx.x < D) {
        float tot = part[0][d] + part[1][d] + part[2][d] + part[3][d];
        g_vmean[bh * D + d] = tot * (1.0f / (float)L);
    }
}

// ---------------------------------------------------------------------------
// Kernel D v2: fill output with broadcast Vmean; 64B (4 x float4) per thread.
// ---------------------------------------------------------------------------
__global__ void __launch_bounds__(256) kD_fill(float4* __restrict__ out4)
{
    int i = (blockIdx.x * blockDim.x + threadIdx.x) * 4;  // base float4 index
    int j   = i & 127;          // 128 float4 per (b,l) row
    int row = i >> 7;
    int b = row >> 11;
    int h = j >> 4, d4 = j & 15;
    const float4* vm4 = (const float4*)g_vmean;
    const float4* src = vm4 + (b * H + h) * 16 + d4;
    #pragma unroll
    for (int u = 0; u < 4; ++u) out4[i + u] = src[u];
}

// ---------------------------------------------------------------------------
// Kernel E: full attention for 8 selected queries per block (unchanged).
// ---------------------------------------------------------------------------
#define UQ 8
#define SMEM_E ((UQ*L + UQ*D + 4*UQ*D + UQ) * 4)

__global__ void __launch_bounds__(256) kE_attn(
    const float* __restrict__ Q, const float* __restrict__ K,
    const float* __restrict__ V, float* __restrict__ out, int U, int UT)
{
    extern __shared__ float sh[];
    float* p    = sh;                    // [UQ][L]
    float* Qs   = p + UQ * L;            // [UQ][D]
    float* red  = Qs + UQ * D;           // [4][UQ][D]
    float* sden = red + 4 * UQ * D;      // [UQ]
    __shared__ int qidx[UQ];

    int bh = blockIdx.x / UT, ut = blockIdx.x % UT;
    int b = bh >> 3, h = bh & 7;
    int t = threadIdx.x;
    int u0 = ut * UQ;
    int nq = U - u0; if (nq > UQ) nq = UQ;

    if (t < UQ) qidx[t] = (t < nq) ? g_top[bh * 64 + u0 + t] : 0;
    __syncthreads();

    for (int i = t; i < UQ * D; i += 256) {
        int j = i >> 6;
        Qs[i] = (j < nq) ? Q[((size_t)(b * L + qidx[j]) * H + h) * D + (i & 63)] : 0.f;
    }
    __syncthreads();

    const float scale = 0.125f;
    for (int k = t; k < L; k += 256) {
        const float4* kp = (const float4*)(K + ((size_t)(b * L + k) * H + h) * D);
        float accj[UQ];
        #pragma unroll
        for (int j = 0; j < UQ; ++j) accj[j] = 0.f;
        #pragma unroll
        for (int c = 0; c < 4; ++c) {
            float4 k0 = kp[c*4+0], k1 = kp[c*4+1], k2 = kp[c*4+2], k3 = kp[c*4+3];
            #pragma unroll
            for (int j = 0; j < UQ; ++j) {
                const float4* qf = (const float4*)(Qs + j * D) + c * 4;
                float4 q0 = qf[0], q1 = qf[1], q2 = qf[2], q3 = qf[3];
                accj[j] += q0.x*k0.x + q0.y*k0.y + q0.z*k0.z + q0.w*k0.w
                         + q1.x*k1.x + q1.y*k1.y + q1.z*k1.z + q1.w*k1.w
                         + q2.x*k2.x + q2.y*k2.y + q2.z*k2.z + q2.w*k2.w
                         + q3.x*k3.x + q3.y*k3.y + q3.z*k3.z + q3.w*k3.w;
            }
        }
        #pragma unroll
        for (int j = 0; j < UQ; ++j) p[j * L + k] = accj[j] * scale;
    }
    __syncthreads();

    int w = t >> 5, lane = t & 31;
    if (w < nq) {
        float* pr = p + w * L;
        float m = -3.402823466e38f;
        for (int k = lane; k < L; k += 32) m = fmaxf(m, pr[k]);
        #pragma unroll
        for (int o = 16; o; o >>= 1) m = fmaxf(m, __shfl_xor_sync(0xffffffffu, m, o));
        float s = 0.f;
        for (int k = lane; k < L; k += 32) {
            float e = __expf(pr[k] - m);
            pr[k] = e;
            s += e;
        }
        #pragma unroll
        for (int o = 16; o; o >>= 1) s += __shfl_xor_sync(0xffffffffu, s, o);
        if (lane == 0) sden[w] = s;
    }
    __syncthreads();

    int d = t & 63, g = t >> 6;
    float acc[UQ];
    #pragma unroll
    for (int j = 0; j < UQ; ++j) acc[j] = 0.f;
    for (int kb = g * 4; kb < L; kb += 16) {
        size_t vb = ((size_t)(b * L + kb) * H + h) * D + d;
        float v0 = V[vb];
        float v1 = V[vb + (size_t)H * D];
        float v2 = V[vb + (size_t)2 * H * D];
        float v3 = V[vb + (size_t)3 * H * D];
        #pragma unroll
        for (int j = 0; j < UQ; ++j) {
            float4 pv = *(const float4*)(p + j * L + kb);
            acc[j] += pv.x * v0 + pv.y * v1 + pv.z * v2 + pv.w * v3;
        }
    }
    #pragma unroll
    for (int j = 0; j < UQ; ++j) red[(g * UQ + j) * D + d] = acc[j];
    __syncthreads();

    for (int i = t; i < nq * D; i += 256) {
        int j = i >> 6, dd = i & 63;
        float s = red[(0 * UQ + j) * D + dd] + red[(1 * UQ + j) * D + dd]
                + red[(2 * UQ + j) * D + dd] + red[(3 * UQ + j) * D + dd];
        out[((size_t)(b * L + qidx[j]) * H + h) * D + dd] = s / sden[j];
    }
}

// ---------------------------------------------------------------------------
extern "C" void kernel_launch(void* const* d_in, const int* in_sizes, int n_in,
                              void* d_out, int out_size)
{
    const float* Q   = (const float*)d_in[0];
    const float* K   = (const float*)d_in[1];
    const float* V   = (const float*)d_in[2];
    const int*   idx = (const int*)d_in[3];
    float* out = (float*)d_out;

    int SK = in_sizes[3] / L;     // sample_k (= 40)
    int U  = SK;                  // u has the same formula (L_Q == L_K)
    if (U > 64) U = 64;
    int UT = (U + UQ - 1) / UQ;

    // A: M scores (smem-staged K chunks)
    cudaFuncSetAttribute(kA_mscore, cudaFuncAttributeMaxDynamicSharedMemorySize, SMEM_A);
    kA_mscore<<<BH * 8, KA_THREADS, SMEM_A>>>(Q, K, idx, SK);
    // C: V mean per (b,h,d)
    kC_vmean<<<BH, 256>>>(V);
    // B: top-U query selection per (b,h)
    kB_topk<<<BH, 256>>>(U);
    // D: broadcast-fill output with Vmean (64B per thread)
    kD_fill<<<(B * L * 128) / (256 * 4), 256>>>((float4*)out);
    // E: full attention for selected queries, overwrite their rows
    cudaFuncSetAttribute(kE_attn, cudaFuncAttributeMaxDynamicSharedMemorySize, SMEM_E);
    kE_attn<<<BH * UT, 256, SMEM_E>>>(Q, K, V, out, U, UT);
}

// round 7
// speedup vs baseline: 2.3375x; 2.3375x over previous
#include <cuda_runtime.h>
#include <cstdint>

// Problem constants (fixed by setup_inputs)
#define B 8
#define L 2048
#define H 8
#define D 64
#define BH (B*H)

// Scratch (device globals — no allocation allowed)
__device__ float g_M[BH * L];        // sparsity measure per (b,h,q)
__device__ int   g_top[BH * 64];     // top-u query indices per (b,h)  (u <= 64)
__device__ float g_vmean[BH * D];    // mean of V over L per (b,h,d)

// ---------------------------------------------------------------------------
// Kernel A v3: M[b,h,q] = max_s(QK_s) - mean_s(QK_s) over sampled keys.
// One warp per (b,h,q); each OCTET (8 lanes) handles one sample -> 4 samples
// in flight per warp. Lane ld holds float4 slices ld and ld+8 of the row
// (full 256B row per octet, coalesced LDG.128 across the warp).
// ---------------------------------------------------------------------------
__global__ void __launch_bounds__(256) kA_mscore(
    const float* __restrict__ Q, const float* __restrict__ K,
    const int* __restrict__ idx, int SK)
{
    const unsigned F = 0xffffffffu;
    int gw   = (blockIdx.x * blockDim.x + threadIdx.x) >> 5;  // [0, BH*L)
    int lane = threadIdx.x & 31;
    int oct  = lane >> 3;          // octet id: which sample of the group of 4
    int ld   = lane & 7;           // lane-in-octet: d-slice owner
    int q  = gw & (L - 1);
    int bh = gw >> 11;             // L = 2^11
    int b  = bh >> 3, h = bh & 7;

    const float4* qp = (const float4*)(Q + ((size_t)(b * L + q) * H + h) * D);
    float4 qa = qp[ld], qb = qp[ld + 8];

    const int* ip = idx + (size_t)q * SK;
    int kq0 = (lane      < SK) ? ip[lane]      : 0;
    int kq1 = (lane + 32 < SK) ? ip[lane + 32] : 0;

    float mx = -3.402823466e38f, sm = 0.f;
    int iters = (SK + 3) >> 2;

    #pragma unroll 5
    for (int it = 0; it < iters; ++it) {
        int s  = it * 4 + oct;
        int i0 = __shfl_sync(F, kq0, s & 31);
        int i1 = __shfl_sync(F, kq1, s & 31);
        int kr = (s < 32) ? i0 : i1;
        bool valid = (s < SK);
        if (!valid) kr = 0;

        const float4* kp = (const float4*)(K + ((size_t)(b * L + kr) * H + h) * D);
        float4 ka = kp[ld], kb = kp[ld + 8];
        float x = qa.x*ka.x + qa.y*ka.y + qa.z*ka.z + qa.w*ka.w
                + qb.x*kb.x + qb.y*kb.y + qb.z*kb.z + qb.w*kb.w;
        // reduce across the 8 lanes of this octet
        x += __shfl_xor_sync(F, x, 4);
        x += __shfl_xor_sync(F, x, 2);
        x += __shfl_xor_sync(F, x, 1);
        if (valid) { mx = fmaxf(mx, x); sm += x; }
    }

    // combine the 4 octet accumulators (each octet's 8 lanes are identical)
    mx = fmaxf(mx, __shfl_xor_sync(F, mx, 8));
    mx = fmaxf(mx, __shfl_xor_sync(F, mx, 16));
    sm += __shfl_xor_sync(F, sm, 8);
    sm += __shfl_xor_sync(F, sm, 16);

    if (lane == 0)
        g_M[gw] = mx - sm / (float)SK;
}

// ---------------------------------------------------------------------------
// Kernel B: top-U per (b,h), register-resident 64-bit sortable keys.
// key = (ordered(value) << 32) | ~index  -> max picks higher value, lower idx.
// ---------------------------------------------------------------------------
__global__ void __launch_bounds__(256) kB_topk(int U)
{
    __shared__ unsigned long long warpbest[8];
    __shared__ unsigned long long sbest;
    int bh = blockIdx.x, t = threadIdx.x, lane = t & 31, w = t >> 5;

    unsigned long long key[8];
    #pragma unroll
    for (int i = 0; i < 8; ++i) {
        int q = t + i * 256;
        unsigned u = __float_as_uint(g_M[(size_t)bh * L + q]);
        u ^= (u >> 31) ? 0xffffffffu : 0x80000000u;
        key[i] = ((unsigned long long)u << 32) | (unsigned)(~q);
    }

    for (int it = 0; it < U; ++it) {
        unsigned long long best = 0;
        #pragma unroll
        for (int i = 0; i < 8; ++i) best = (key[i] > best) ? key[i] : best;
        #pragma unroll
        for (int o = 16; o; o >>= 1) {
            unsigned long long oth = __shfl_xor_sync(0xffffffffu, best, o);
            best = (oth > best) ? oth : best;
        }
        if (lane == 0) warpbest[w] = best;
        __syncthreads();
        if (t < 32) {
            unsigned long long bb = (t < 8) ? warpbest[t] : 0ull;
            #pragma unroll
            for (int o = 4; o; o >>= 1) {
                unsigned long long oth = __shfl_xor_sync(0xffffffffu, bb, o);
                bb = (oth > bb) ? oth : bb;
            }
            if (t == 0) {
                sbest = bb;
                g_top[bh * 64 + it] = (int)(~(unsigned)(bb & 0xffffffffu));
            }
        }
        __syncthreads();
        unsigned long long win = sbest;
        #pragma unroll
        for (int i = 0; i < 8; ++i) if (key[i] == win) key[i] = 0ull;
    }
}

// ---------------------------------------------------------------------------
// Kernel C: Vmean[b,h,d] = mean over l of V[b,l,h,d]. One block per (b,h).
// ---------------------------------------------------------------------------
__global__ void __launch_bounds__(256) kC_vmean(const float* __restrict__ V)
{
    __shared__ float part[4][D];
    int bh = blockIdx.x, b = bh >> 3, h = bh & 7;
    int d = threadIdx.x & 63, g = threadIdx.x >> 6;
    float s = 0.f;
    for (int l = g; l < L; l += 4)
        s += V[((size_t)(b * L + l) * H + h) * D + d];
    part[g][d] = s;
    __syncthreads();
    if (threadIdx.x < D) {
        float tot = part[0][d] + part[1][d] + part[2][d] + part[3][d];
        g_vmean[bh * D + d] = tot * (1.0f / (float)L);
    }
}

// ---------------------------------------------------------------------------
// Kernel D: fill output with broadcast Vmean (1 float4 per thread — the
// measured-fastest variant).
// ---------------------------------------------------------------------------
__global__ void __launch_bounds__(256) kD_fill(float4* __restrict__ out4)
{
    int i = blockIdx.x * blockDim.x + threadIdx.x;     // [0, B*L*128)
    int j   = i & 127;          // 128 float4 per (b,l) row
    int row = i >> 7;
    int b = row >> 11;
    int h = j >> 4, d4 = j & 15;
    const float4* vm4 = (const float4*)g_vmean;
    out4[i] = vm4[(b * H + h) * 16 + d4];
}

// ---------------------------------------------------------------------------
// Kernel E: full attention for 8 selected queries per block.
// ---------------------------------------------------------------------------
#define UQ 8
#define SMEM_E ((UQ*L + UQ*D + 4*UQ*D + UQ) * 4)

__global__ void __launch_bounds__(256) kE_attn(
    const float* __restrict__ Q, const float* __restrict__ K,
    const float* __restrict__ V, float* __restrict__ out, int U, int UT)
{
    extern __shared__ float sh[];
    float* p    = sh;                    // [UQ][L] unnormalized probs
    float* Qs   = p + UQ * L;            // [UQ][D]
    float* red  = Qs + UQ * D;           // [4][UQ][D]
    float* sden = red + 4 * UQ * D;      // [UQ]
    __shared__ int qidx[UQ];

    int bh = blockIdx.x / UT, ut = blockIdx.x % UT;
    int b = bh >> 3, h = bh & 7;
    int t = threadIdx.x;
    int u0 = ut * UQ;
    int nq = U - u0; if (nq > UQ) nq = UQ;

    if (t < UQ) qidx[t] = (t < nq) ? g_top[bh * 64 + u0 + t] : 0;
    __syncthreads();

    for (int i = t; i < UQ * D; i += 256) {
        int j = i >> 6;
        Qs[i] = (j < nq) ? Q[((size_t)(b * L + qidx[j]) * H + h) * D + (i & 63)] : 0.f;
    }
    __syncthreads();

    const float scale = 0.125f;  // 1/sqrt(64)
    for (int k = t; k < L; k += 256) {
        const float4* kp = (const float4*)(K + ((size_t)(b * L + k) * H + h) * D);
        float accj[UQ];
        #pragma unroll
        for (int j = 0; j < UQ; ++j) accj[j] = 0.f;
        #pragma unroll
        for (int c = 0; c < 4; ++c) {
            float4 k0 = kp[c*4+0], k1 = kp[c*4+1], k2 = kp[c*4+2], k3 = kp[c*4+3];
            #pragma unroll
            for (int j = 0; j < UQ; ++j) {
                const float4* qf = (const float4*)(Qs + j * D) + c * 4;
                float4 q0 = qf[0], q1 = qf[1], q2 = qf[2], q3 = qf[3];
                accj[j] += q0.x*k0.x + q0.y*k0.y + q0.z*k0.z + q0.w*k0.w
                         + q1.x*k1.x + q1.y*k1.y + q1.z*k1.z + q1.w*k1.w
                         + q2.x*k2.x + q2.y*k2.y + q2.z*k2.z + q2.w*k2.w
                         + q3.x*k3.x + q3.y*k3.y + q3.z*k3.z + q3.w*k3.w;
            }
        }
        #pragma unroll
        for (int j = 0; j < UQ; ++j) p[j * L + k] = accj[j] * scale;
    }
    __syncthreads();

    int w = t >> 5, lane = t & 31;
    if (w < nq) {
        float* pr = p + w * L;
        float m = -3.402823466e38f;
        for (int k = lane; k < L; k += 32) m = fmaxf(m, pr[k]);
        #pragma unroll
        for (int o = 16; o; o >>= 1) m = fmaxf(m, __shfl_xor_sync(0xffffffffu, m, o));
        float s = 0.f;
        for (int k = lane; k < L; k += 32) {
            float e = __expf(pr[k] - m);
            pr[k] = e;
            s += e;
        }
        #pragma unroll
        for (int o = 16; o; o >>= 1) s += __shfl_xor_sync(0xffffffffu, s, o);
        if (lane == 0) sden[w] = s;
    }
    __syncthreads();

    int d = t & 63, g = t >> 6;
    float acc[UQ];
    #pragma unroll
    for (int j = 0; j < UQ; ++j) acc[j] = 0.f;
    for (int kb = g * 4; kb < L; kb += 16) {
        size_t vb = ((size_t)(b * L + kb) * H + h) * D + d;
        float v0 = V[vb];
        float v1 = V[vb + (size_t)H * D];
        float v2 = V[vb + (size_t)2 * H * D];
        float v3 = V[vb + (size_t)3 * H * D];
        #pragma unroll
        for (int j = 0; j < UQ; ++j) {
            float4 pv = *(const float4*)(p + j * L + kb);   // warp-uniform -> broadcast
            acc[j] += pv.x * v0 + pv.y * v1 + pv.z * v2 + pv.w * v3;
        }
    }
    #pragma unroll
    for (int j = 0; j < UQ; ++j) red[(g * UQ + j) * D + d] = acc[j];
    __syncthreads();

    for (int i = t; i < nq * D; i += 256) {
        int j = i >> 6, dd = i & 63;
        float s = red[(0 * UQ + j) * D + dd] + red[(1 * UQ + j) * D + dd]
                + red[(2 * UQ + j) * D + dd] + red[(3 * UQ + j) * D + dd];
        out[((size_t)(b * L + qidx[j]) * H + h) * D + dd] = s / sden[j];
    }
}

// ---------------------------------------------------------------------------
extern "C" void kernel_launch(void* const* d_in, const int* in_sizes, int n_in,
                              void* d_out, int out_size)
{
    const float* Q   = (const float*)d_in[0];
    const float* K   = (const float*)d_in[1];
    const float* V   = (const float*)d_in[2];
    const int*   idx = (const int*)d_in[3];
    float* out = (float*)d_out;

    int SK = in_sizes[3] / L;     // sample_k (= 40)
    int U  = SK;                  // u has the same formula (L_Q == L_K)
    if (U > 64) U = 64;
    int UT = (U + UQ - 1) / UQ;   // u-tiles per (b,h)

    // A: M scores (octet-parallel gathered QK over samples)
    kA_mscore<<<(BH * L) / 8, 256>>>(Q, K, idx, SK);
    // C: V mean per (b,h,d)
    kC_vmean<<<BH, 256>>>(V);
    // B: top-U query selection per (b,h)
    kB_topk<<<BH, 256>>>(U);
    // D: broadcast-fill output with Vmean
    kD_fill<<<(B * L * 128) / 256, 256>>>((float4*)out);
    // E: full attention for selected queries, overwrite their rows
    cudaFuncSetAttribute(kE_attn, cudaFuncAttributeMaxDynamicSharedMemorySize, SMEM_E);
    kE_attn<<<BH * UT, 256, SMEM_E>>>(Q, K, V, out, U, UT);
}